// round 1
// baseline (speedup 1.0000x reference)
#include <cuda_runtime.h>
#include <cuda_bf16.h>

// Problem dims (fixed by the reference setup)
#define T_DIM 8192
#define H_DIM 1024
#define D_DIM 1024
#define E_DIM 8
#define N1    (2 * D_DIM)      // 2048, gate_up output width per expert
#define K2    (E_DIM * D_DIM)  // 8192, concatenated K for the down GEMM

#define ALPHA 1.702f
#define LIMIT 7.0f

// Scratch: A'[t, e*D + d] = rw[t,e] * (up+1)*glu   (256 MiB, fp32)
__device__ float g_inter[(size_t)T_DIM * K2];

// ---------------------------------------------------------------------------
// GEMM1: per expert e, C = hs[T,H] @ W1_e[H,2D]; epilogue applies bias,
// clipped-GLU on interleaved (even=gate, odd=up) columns, folds routing
// weight, writes g_inter[t, e*D + n/2].
// Tiling: 128x128 block tile, BK=8, 256 threads, 8x8 per thread.
// ---------------------------------------------------------------------------
__global__ __launch_bounds__(256) void gemm1_kernel(
    const float* __restrict__ hs,   // [T, H]
    const float* __restrict__ w1,   // [E, H, 2D]
    const float* __restrict__ b1,   // [E, 2D]
    const float* __restrict__ rw)   // [T, E]
{
    const int e  = blockIdx.z;
    const int bn = blockIdx.x;   // 0..15  (N1/128)
    const int bm = blockIdx.y;   // 0..63  (T/128)

    const float* B = w1 + (size_t)e * H_DIM * N1;
    const float* b1e = b1 + (size_t)e * N1;

    __shared__ float As[8][128];
    __shared__ float Bs[8][128];

    const int tid = threadIdx.x;
    const int tx = tid % 16;
    const int ty = tid / 16;

    // global-load roles
    const int a_row = tid % 128;          // row within A tile
    const int a_k4  = (tid / 128) * 4;    // k offset (0 or 4)
    const int b_row = tid / 32;           // k row within B tile (0..7)
    const int b_col = (tid % 32) * 4;     // col within B tile

    float acc[8][8];
#pragma unroll
    for (int i = 0; i < 8; i++)
#pragma unroll
        for (int j = 0; j < 8; j++) acc[i][j] = 0.f;

    const int grow = bm * 128;
    const int gcol = bn * 128;

    for (int k0 = 0; k0 < H_DIM; k0 += 8) {
        // load A tile (transposed into As[k][m])
        float4 av = *reinterpret_cast<const float4*>(
            &hs[(size_t)(grow + a_row) * H_DIM + k0 + a_k4]);
        As[a_k4 + 0][a_row] = av.x;
        As[a_k4 + 1][a_row] = av.y;
        As[a_k4 + 2][a_row] = av.z;
        As[a_k4 + 3][a_row] = av.w;
        // load B tile
        *reinterpret_cast<float4*>(&Bs[b_row][b_col]) =
            *reinterpret_cast<const float4*>(
                &B[(size_t)(k0 + b_row) * N1 + gcol + b_col]);
        __syncthreads();

#pragma unroll
        for (int kk = 0; kk < 8; kk++) {
            float4 a0 = *reinterpret_cast<const float4*>(&As[kk][ty * 4]);
            float4 a1 = *reinterpret_cast<const float4*>(&As[kk][ty * 4 + 64]);
            float4 b0 = *reinterpret_cast<const float4*>(&Bs[kk][tx * 4]);
            float4 b1v = *reinterpret_cast<const float4*>(&Bs[kk][tx * 4 + 64]);
            float a_f[8] = {a0.x, a0.y, a0.z, a0.w, a1.x, a1.y, a1.z, a1.w};
            float b_f[8] = {b0.x, b0.y, b0.z, b0.w, b1v.x, b1v.y, b1v.z, b1v.w};
#pragma unroll
            for (int i = 0; i < 8; i++)
#pragma unroll
                for (int j = 0; j < 8; j++)
                    acc[i][j] = fmaf(a_f[i], b_f[j], acc[i][j]);
        }
        __syncthreads();
    }

    // epilogue: bias + clipped GLU + routing-weight fold
#pragma unroll
    for (int i = 0; i < 8; i++) {
        const int row = grow + ((i < 4) ? (ty * 4 + i) : (ty * 4 + 64 + i - 4));
        const float rwv = rw[(size_t)row * E_DIM + e];
#pragma unroll
        for (int jg = 0; jg < 2; jg++) {
            const int cb = gcol + tx * 4 + jg * 64;  // even base column
            const int jb = jg * 4;
#pragma unroll
            for (int p = 0; p < 4; p += 2) {
                float gate = acc[i][jb + p]     + b1e[cb + p];
                float up   = acc[i][jb + p + 1] + b1e[cb + p + 1];
                gate = fminf(gate, LIMIT);
                up   = fminf(fmaxf(up, -LIMIT), LIMIT);
                float glu = gate / (1.f + __expf(-gate * ALPHA));
                float val = (up + 1.f) * glu * rwv;
                const int d = (cb + p) >> 1;  // 0..1023
                g_inter[(size_t)row * K2 + (size_t)e * D_DIM + d] = val;
            }
        }
    }
}

// ---------------------------------------------------------------------------
// GEMM2: out[T,H] = g_inter[T, 8192] @ down[8192, 1024]
//        + sum_e rw[t,e] * b2[e, h]
// (down_proj [E,D,H] viewed flat as [E*D, H] row-major — exactly the needed K
//  ordering since g_inter columns are e*D + d.)
// ---------------------------------------------------------------------------
__global__ __launch_bounds__(256) void gemm2_kernel(
    const float* __restrict__ w2,   // [E*D, H] = [8192, 1024]
    const float* __restrict__ b2,   // [E, H]
    const float* __restrict__ rw,   // [T, E]
    float* __restrict__ out)        // [T, H]
{
    const int bn = blockIdx.x;   // 0..7  (H/128)
    const int bm = blockIdx.y;   // 0..63 (T/128)

    __shared__ float As[8][128];
    __shared__ float Bs[8][128];

    const int tid = threadIdx.x;
    const int tx = tid % 16;
    const int ty = tid / 16;

    const int a_row = tid % 128;
    const int a_k4  = (tid / 128) * 4;
    const int b_row = tid / 32;
    const int b_col = (tid % 32) * 4;

    float acc[8][8];
#pragma unroll
    for (int i = 0; i < 8; i++)
#pragma unroll
        for (int j = 0; j < 8; j++) acc[i][j] = 0.f;

    const int grow = bm * 128;
    const int gcol = bn * 128;

    for (int k0 = 0; k0 < K2; k0 += 8) {
        float4 av = *reinterpret_cast<const float4*>(
            &g_inter[(size_t)(grow + a_row) * K2 + k0 + a_k4]);
        As[a_k4 + 0][a_row] = av.x;
        As[a_k4 + 1][a_row] = av.y;
        As[a_k4 + 2][a_row] = av.z;
        As[a_k4 + 3][a_row] = av.w;
        *reinterpret_cast<float4*>(&Bs[b_row][b_col]) =
            *reinterpret_cast<const float4*>(
                &w2[(size_t)(k0 + b_row) * H_DIM + gcol + b_col]);
        __syncthreads();

#pragma unroll
        for (int kk = 0; kk < 8; kk++) {
            float4 a0 = *reinterpret_cast<const float4*>(&As[kk][ty * 4]);
            float4 a1 = *reinterpret_cast<const float4*>(&As[kk][ty * 4 + 64]);
            float4 b0 = *reinterpret_cast<const float4*>(&Bs[kk][tx * 4]);
            float4 b1v = *reinterpret_cast<const float4*>(&Bs[kk][tx * 4 + 64]);
            float a_f[8] = {a0.x, a0.y, a0.z, a0.w, a1.x, a1.y, a1.z, a1.w};
            float b_f[8] = {b0.x, b0.y, b0.z, b0.w, b1v.x, b1v.y, b1v.z, b1v.w};
#pragma unroll
            for (int i = 0; i < 8; i++)
#pragma unroll
                for (int j = 0; j < 8; j++)
                    acc[i][j] = fmaf(a_f[i], b_f[j], acc[i][j]);
        }
        __syncthreads();
    }

    // epilogue: add routing-weighted down bias, write out
#pragma unroll
    for (int i = 0; i < 8; i++) {
        const int row = grow + ((i < 4) ? (ty * 4 + i) : (ty * 4 + 64 + i - 4));
        float rwe[E_DIM];
#pragma unroll
        for (int ee = 0; ee < E_DIM; ee++)
            rwe[ee] = rw[(size_t)row * E_DIM + ee];
#pragma unroll
        for (int jg = 0; jg < 2; jg++) {
            const int cb = gcol + tx * 4 + jg * 64;
            const int jb = jg * 4;
            float4 v;
            float* vp = &v.x;
#pragma unroll
            for (int p = 0; p < 4; p++) {
                float bias = 0.f;
#pragma unroll
                for (int ee = 0; ee < E_DIM; ee++)
                    bias = fmaf(rwe[ee], b2[(size_t)ee * H_DIM + cb + p], bias);
                vp[p] = acc[i][jb + p] + bias;
            }
            *reinterpret_cast<float4*>(&out[(size_t)row * H_DIM + cb]) = v;
        }
    }
}

extern "C" void kernel_launch(void* const* d_in, const int* in_sizes, int n_in,
                              void* d_out, int out_size)
{
    const float* hs = (const float*)d_in[0];   // hidden_states [T,H]
    const float* rw = (const float*)d_in[1];   // routing_weights [T,E]
    const float* w1 = (const float*)d_in[2];   // gate_up_proj [E,H,2D]
    const float* b1 = (const float*)d_in[3];   // gate_up_proj_bias [E,2D]
    const float* w2 = (const float*)d_in[4];   // down_proj [E,D,H]
    const float* b2 = (const float*)d_in[5];   // down_proj_bias [E,H]
    float* out = (float*)d_out;                // [T,1,H] fp32

    dim3 g1(N1 / 128, T_DIM / 128, E_DIM);     // (16, 64, 8)
    gemm1_kernel<<<g1, 256>>>(hs, w1, b1, rw);

    dim3 g2(H_DIM / 128, T_DIM / 128);         // (8, 64)
    gemm2_kernel<<<g2, 256>>>(w2, b2, rw, out);
}